// round 4
// baseline (speedup 1.0000x reference)
#include <cuda_runtime.h>
#include <cstdint>
#include <math.h>

#define BATCH   16
#define NCLS    64
#define CDF     128
#define EDIM    1024

// ===================== common helpers =====================
__device__ __forceinline__ uint32_t f2tf32(float f) {
    uint32_t u; asm("cvt.rna.tf32.f32 %0, %1;" : "=r"(u) : "f"(f)); return u;
}
__device__ __forceinline__ float gelu_erf(float v) {
    return 0.5f * v * (1.0f + erff(v * 0.7071067811865476f));
}

// Feature gate: tcgen05 only exists in arch-specific (sm_103a/sm_100a) passes.
#if defined(__CUDA_ARCH_FEAT_SM103_ALL) || defined(__CUDA_ARCH_FEAT_SM100_ALL) || defined(__CUDA_ARCH_FEAT_SM101_ALL)
#define TCGEN05_OK 1
#else
#define TCGEN05_OK 0
#endif

// ======================================================================
// Path A: tcgen05 tf32 warp-specialized kernel (sm_103a passes only)
// ======================================================================
#define NCHUNK  256        // N columns per TMEM chunk (4 chunks total)
#define KT      32         // K per SMEM tile (4 tcgen05 K=8 steps)
#define NSTAGE  4
#define THREADS_TC 288     // warps 0-3 epilogue, 4-7 stagers, 8 MMA

#define OFF_TMEM   0
#define OFF_MB     8                    // per stage s: full @ 8+16s, empty @ 8+16s+8
#define OFF_CHK    72                   // chunk_done[2] @ 72+8p
#define OFF_EPI    88                   // epi_done[2]   @ 88+8p
#define OFF_SB1    128                  // float[2][256]
#define OFF_SW2    (128 + 2048)         // float[2][256]
#define OFF_TILE   8192
#define STAGE_BYTES 49152               // A 16KB + B 32KB, 1KB aligned
#define BTILE_OFF   16384
#define SMEM_TOTAL (OFF_TILE + NSTAGE * STAGE_BYTES)   // 204800

// idesc: kind::tf32, D=F32(1)@[4], atype=TF32(2)@[7], btype=TF32(2)@[10],
// N>>3 @[17], M>>4 @[24]
#define IDESC_TF32 ((1u<<4) | (2u<<7) | (2u<<10) | ((NCHUNK/8)<<17) | ((128/16)<<24))

#if TCGEN05_OK
__device__ __forceinline__ uint64_t make_desc(uint32_t addr) {
    return (uint64_t(2) << 61) | (uint64_t(1) << 46) | (uint64_t(64) << 32)
         | (uint64_t(1) << 16) | ((uint64_t)(addr >> 4) & 0x3FFF);
}
__device__ __forceinline__ uint32_t smem_u32(const void* p) {
    uint32_t a;
    asm("{ .reg .u64 t; cvta.to.shared.u64 t, %1; cvt.u32.u64 %0, t; }" : "=r"(a) : "l"(p));
    return a;
}
__device__ __forceinline__ void sts128(uint32_t a, uint32_t x, uint32_t y, uint32_t z, uint32_t w) {
    asm volatile("st.shared.v4.b32 [%0], {%1,%2,%3,%4};" :: "r"(a), "r"(x), "r"(y), "r"(z), "r"(w) : "memory");
}
__device__ __forceinline__ void mbar_init(uint32_t a, uint32_t cnt) {
    asm volatile("mbarrier.init.shared.b64 [%0], %1;" :: "r"(a), "r"(cnt) : "memory");
}
__device__ __forceinline__ void mbar_arrive(uint32_t a) {
    asm volatile("mbarrier.arrive.shared.b64 _, [%0];" :: "r"(a) : "memory");
}
__device__ __forceinline__ void mbar_wait(uint32_t a, uint32_t parity) {
    asm volatile(
        "{\n\t.reg .pred P;\n\t"
        "WL%=:\n\t"
        "mbarrier.try_wait.parity.acquire.cta.shared::cta.b64 P, [%0], %1, 0x989680;\n\t"
        "@P bra.uni WD%=;\n\t"
        "bra.uni WL%=;\n\t"
        "WD%=:\n\t}" :: "r"(a), "r"(parity) : "memory");
}
__device__ __forceinline__ void fence_async_proxy() {
    asm volatile("fence.proxy.async.shared::cta;" ::: "memory");
}
__device__ __forceinline__ void tc_commit(uint32_t mbar) {
    asm volatile("tcgen05.commit.cta_group::1.mbarrier::arrive::one.shared::cluster.b64 [%0];"
                 :: "r"(mbar) : "memory");
}
__device__ __forceinline__ void mma_tf32_ss(uint32_t d, uint64_t ad, uint64_t bd,
                                            uint32_t idesc, uint32_t enable) {
    asm volatile(
        "{\n\t.reg .pred p;\n\t"
        "setp.ne.u32 p, %5, 0;\n\t"
        "tcgen05.mma.cta_group::1.kind::tf32 [%0], %1, %2, %3, {%4,%4,%4,%4}, p;\n\t}"
        :: "r"(d), "l"(ad), "l"(bd), "r"(idesc), "r"(0u), "r"(enable) : "memory");
}
#endif  // TCGEN05_OK

__global__ void __launch_bounds__(THREADS_TC, 1)
mlp_head_tc(const float* __restrict__ x,
            const float* __restrict__ W1,
            const float* __restrict__ b1,
            const float* __restrict__ W2,
            const float* __restrict__ b2,
            float* __restrict__ out)
{
#if TCGEN05_OK
    extern __shared__ char smem[];
    const uint32_t sb = smem_u32(smem);

    const int tid  = threadIdx.x;
    const int warp = tid >> 5;
    const int lane = tid & 31;
    const int b    = blockIdx.x;
    const int c    = blockIdx.y;

    const float* Abase = x  + ((size_t)b * (NCLS * CDF) + (size_t)c * CDF) * EDIM;
    const float* W1c   = W1 + (size_t)c * EDIM * EDIM;

    float* sb1s = (float*)(smem + OFF_SB1);
    float* sw2s = (float*)(smem + OFF_SW2);

    if (warp == 8) {
        asm volatile("tcgen05.alloc.cta_group::1.sync.aligned.shared::cta.b32 [%0], %1;"
                     :: "r"(sb + OFF_TMEM), "r"(512u) : "memory");
    }
    if (tid == 0) {
        #pragma unroll
        for (int s = 0; s < NSTAGE; ++s) {
            mbar_init(sb + OFF_MB + s * 16,     128);  // full: 128 staging threads
            mbar_init(sb + OFF_MB + s * 16 + 8, 1);    // empty: 1 commit
        }
        mbar_init(sb + OFF_CHK + 0, 1);   mbar_init(sb + OFF_CHK + 8, 1);
        mbar_init(sb + OFF_EPI + 0, 128); mbar_init(sb + OFF_EPI + 8, 128);
    }
    __syncthreads();

    uint32_t tmem;
    asm volatile("ld.shared.b32 %0, [%1];" : "=r"(tmem) : "r"(sb + OFF_TMEM));

    if (warp >= 4 && warp < 8) {
        // ========== STAGING (warps 4-7, 128 threads), SW-pipelined ==========
        const int local = tid - 128;
        const int q  = local & 7;    // 16B quad within 128B row (A)
        const int r8 = local >> 3;   // 0..15
        const int NTILES = 4 * (EDIM / KT);   // 128

        float4 abuf[8];
        float  bbuf[64];

        // ---- register prefetch of tile g (no SMEM touched) ----
        auto load_tile = [&](int g) {
            const int gi = (g < NTILES) ? g : (NTILES - 1);
            const int ci = gi >> 5;
            const int k0 = (gi & 31) * KT;
            const int nb = ci * NCHUNK;
            const float* Ak = Abase + k0 + (size_t)r8 * EDIM + q * 4;
            #pragma unroll
            for (int ps = 0; ps < 8; ++ps)
                abuf[ps] = *(const float4*)(Ak + (size_t)ps * 16 * EDIM);
            const float* Bp0 = W1c + (size_t)k0 * EDIM + nb + local;
            #pragma unroll
            for (int rr = 0; rr < 2; ++rr) {
                const float* Bp = Bp0 + rr * 128;
                #pragma unroll
                for (int kk = 0; kk < 32; ++kk)
                    bbuf[rr * 32 + kk] = Bp[(size_t)kk * EDIM];
            }
        };

        load_tile(0);
        for (int g = 0; g < NTILES; ++g) {
            const int s = g & (NSTAGE - 1);
            const int r = g >> 2;                      // ring round
            mbar_wait(sb + OFF_MB + s * 16 + 8, (r & 1) ^ 1);   // empty

            const uint32_t a_sm = sb + OFF_TILE + s * STAGE_BYTES;
            const uint32_t b_sm = a_sm + BTILE_OFF;

            // ---- A tile: 128 rows x 32 k (tf32-RNA, SW128) ----
            #pragma unroll
            for (int ps = 0; ps < 8; ++ps) {
                const int row = ps * 16 + r8;
                uint32_t off = row * 128 + q * 16;
                off ^= (off >> 3) & 0x70;
                sts128(a_sm + off, f2tf32(abuf[ps].x), f2tf32(abuf[ps].y),
                       f2tf32(abuf[ps].z), f2tf32(abuf[ps].w));
            }
            // ---- B tile: 256 n-rows x 32 k (row-major n, SW128) ----
            #pragma unroll
            for (int rr = 0; rr < 2; ++rr) {
                const int rowb = local + rr * 128;
                #pragma unroll
                for (int kq = 0; kq < 8; ++kq) {
                    uint32_t off = rowb * 128 + kq * 16;
                    off ^= (off >> 3) & 0x70;
                    sts128(b_sm + off,
                           f2tf32(bbuf[rr * 32 + kq * 4 + 0]),
                           f2tf32(bbuf[rr * 32 + kq * 4 + 1]),
                           f2tf32(bbuf[rr * 32 + kq * 4 + 2]),
                           f2tf32(bbuf[rr * 32 + kq * 4 + 3]));
                }
            }
            fence_async_proxy();
            mbar_arrive(sb + OFF_MB + s * 16);   // full
            load_tile(g + 1);                     // overlap next tile's GMEM latency
        }
    } else if (warp == 8) {
        // ================= MMA ISSUE (warp 8, lane 0) =================
        if (lane == 0) {
            uint64_t ad[NSTAGE], bd[NSTAGE];
            #pragma unroll
            for (int s = 0; s < NSTAGE; ++s) {
                ad[s] = make_desc(sb + OFF_TILE + s * STAGE_BYTES);
                bd[s] = make_desc(sb + OFF_TILE + s * STAGE_BYTES + BTILE_OFF);
            }
            int g = 0;
            for (int ci = 0; ci < 4; ++ci) {
                const int p = ci & 1;
                if (ci >= 2) {
                    mbar_wait(sb + OFF_EPI + p * 8, 0);   // D region free
                    asm volatile("tcgen05.fence::after_thread_sync;" ::: "memory");
                }
                const uint32_t dt = tmem + p * NCHUNK;
                for (int kt = 0; kt < 32; ++kt, ++g) {
                    const int s = g & (NSTAGE - 1);
                    const int r = g >> 2;
                    mbar_wait(sb + OFF_MB + s * 16, r & 1);   // full
                    #pragma unroll
                    for (int j = 0; j < 4; ++j) {
                        mma_tf32_ss(dt, ad[s] + j * 2, bd[s] + j * 2,
                                    IDESC_TF32, (kt > 0 || j > 0) ? 1u : 0u);
                    }
                    tc_commit(sb + OFF_MB + s * 16 + 8);      // -> empty
                }
                tc_commit(sb + OFF_CHK + p * 8);              // -> chunk_done
            }
        }
    } else {
        // ================= EPILOGUE (warps 0-3, 128 threads) =================
        float accum = 0.0f;
        for (int ci = 0; ci < 4; ++ci) {
            const int p = ci & 1;
            asm volatile("bar.sync 1, 128;" ::: "memory");
            sb1s[p * 256 + 2 * tid]     = b1[(size_t)c * EDIM + ci * NCHUNK + 2 * tid];
            sb1s[p * 256 + 2 * tid + 1] = b1[(size_t)c * EDIM + ci * NCHUNK + 2 * tid + 1];
            sw2s[p * 256 + 2 * tid]     = W2[(size_t)c * EDIM + ci * NCHUNK + 2 * tid];
            sw2s[p * 256 + 2 * tid + 1] = W2[(size_t)c * EDIM + ci * NCHUNK + 2 * tid + 1];
            asm volatile("bar.sync 1, 128;" ::: "memory");

            mbar_wait(sb + OFF_CHK + p * 8, (ci >> 1) & 1);
            asm volatile("tcgen05.fence::after_thread_sync;" ::: "memory");

            #pragma unroll
            for (int blk = 0; blk < NCHUNK / 32; ++blk) {
                uint32_t rg[32];
                asm volatile(
                    "tcgen05.ld.sync.aligned.32x32b.x32.b32 "
                    "{%0,%1,%2,%3,%4,%5,%6,%7,%8,%9,%10,%11,%12,%13,%14,%15,"
                    "%16,%17,%18,%19,%20,%21,%22,%23,%24,%25,%26,%27,%28,%29,%30,%31}, [%32];"
                    : "=r"(rg[0]),"=r"(rg[1]),"=r"(rg[2]),"=r"(rg[3]),"=r"(rg[4]),"=r"(rg[5]),
                      "=r"(rg[6]),"=r"(rg[7]),"=r"(rg[8]),"=r"(rg[9]),"=r"(rg[10]),"=r"(rg[11]),
                      "=r"(rg[12]),"=r"(rg[13]),"=r"(rg[14]),"=r"(rg[15]),"=r"(rg[16]),"=r"(rg[17]),
                      "=r"(rg[18]),"=r"(rg[19]),"=r"(rg[20]),"=r"(rg[21]),"=r"(rg[22]),"=r"(rg[23]),
                      "=r"(rg[24]),"=r"(rg[25]),"=r"(rg[26]),"=r"(rg[27]),"=r"(rg[28]),"=r"(rg[29]),
                      "=r"(rg[30]),"=r"(rg[31])
                    : "r"(tmem + p * NCHUNK + blk * 32));
                asm volatile("tcgen05.wait::ld.sync.aligned;" ::: "memory");
                #pragma unroll
                for (int j = 0; j < 32; ++j) {
                    const int col = p * 256 + blk * 32 + j;
                    float v = __uint_as_float(rg[j]) + sb1s[col];
                    accum += gelu_erf(v) * sw2s[col];
                }
            }
            asm volatile("tcgen05.fence::before_thread_sync;" ::: "memory");
            mbar_arrive(sb + OFF_EPI + p * 8);
        }
        const int row = warp * 32 + lane;
        out[(size_t)b * (NCLS * CDF) + (size_t)c * CDF + row] = accum + b2[c];
    }

    __syncthreads();
    if (warp == 8) {
        asm volatile("tcgen05.relinquish_alloc_permit.cta_group::1.sync.aligned;" ::: "memory");
        asm volatile("tcgen05.dealloc.cta_group::1.sync.aligned.b32 %0, %1;" :: "r"(tmem), "r"(512u));
    }
#else
    (void)x; (void)W1; (void)b1; (void)W2; (void)b2; (void)out;
#endif
}

// ======================================================================
// Path B: fallback mma.sync tf32 kernel (active only on non-'a' passes)
// ======================================================================
#define MT      128
#define NT      128
#define KTF     32
#define THREADS_FB 256
#define SROW    36

#if !TCGEN05_OK
__device__ __forceinline__ void mma_tf32_frag(float4& d,
                                              uint32_t a0, uint32_t a1, uint32_t a2, uint32_t a3,
                                              uint32_t b0, uint32_t b1) {
    asm volatile(
        "mma.sync.aligned.m16n8k8.row.col.f32.tf32.tf32.f32 "
        "{%0,%1,%2,%3}, {%4,%5,%6,%7}, {%8,%9}, {%0,%1,%2,%3};\n"
        : "+f"(d.x), "+f"(d.y), "+f"(d.z), "+f"(d.w)
        : "r"(a0), "r"(a1), "r"(a2), "r"(a3), "r"(b0), "r"(b1));
}
#endif

__global__ void __launch_bounds__(THREADS_FB, 2)
mlp_head_fb(const float* __restrict__ x,
            const float* __restrict__ W1,
            const float* __restrict__ b1,
            const float* __restrict__ W2,
            const float* __restrict__ b2,
            float* __restrict__ out)
{
#if !TCGEN05_OK
    __shared__ uint32_t As[MT * SROW];
    __shared__ uint32_t Bs[NT * SROW];
    __shared__ float sb1[NT];
    __shared__ float sw2[NT];
    __shared__ float s_out[MT];

    const int b    = blockIdx.x;
    const int c    = blockIdx.y;
    const int tid  = threadIdx.x;
    const int lane = tid & 31;
    const int warp = tid >> 5;
    const int wm   = warp >> 1;
    const int wn   = warp & 1;

    const float* Abase = x  + ((size_t)b * (NCLS * CDF) + (size_t)c * CDF) * EDIM;
    const float* W1c   = W1 + (size_t)c * EDIM * EDIM;

    if (tid < MT) s_out[tid] = 0.0f;

    for (int n0 = 0; n0 < EDIM; n0 += NT) {
        float4 acc[2][8];
        #pragma unroll
        for (int mi = 0; mi < 2; ++mi)
            #pragma unroll
            for (int ni = 0; ni < 8; ++ni)
                acc[mi][ni] = make_float4(0.f, 0.f, 0.f, 0.f);

        for (int k0 = 0; k0 < EDIM; k0 += KTF) {
            __syncthreads();
            {
                const float* Ak = Abase + k0;
                const int kq = tid & 7;
                const int r0 = tid >> 3;
                #pragma unroll
                for (int it = 0; it < 4; ++it) {
                    int r = r0 + it * 32;
                    float4 v = *(const float4*)(Ak + (size_t)r * EDIM + kq * 4);
                    uint32_t* dst = &As[r * SROW + kq];
                    dst[0]  = f2tf32(v.x);
                    dst[8]  = f2tf32(v.y);
                    dst[16] = f2tf32(v.z);
                    dst[24] = f2tf32(v.w);
                }
            }
            {
                const int n  = tid & 127;
                const int kh = tid >> 7;
                const float* Bp = W1c + (size_t)k0 * EDIM + n0 + n;
                #pragma unroll
                for (int kk = 0; kk < 4; ++kk) {
                    int kbase = kk * 8 + kh * 4;
                    #pragma unroll
                    for (int i = 0; i < 4; ++i) {
                        float v = Bp[(size_t)(kbase + i) * EDIM];
                        Bs[n * SROW + i * 8 + kk * 2 + kh] = f2tf32(v);
                    }
                }
            }
            if (k0 == 0 && tid < NT) {
                sb1[tid] = b1[(size_t)c * EDIM + n0 + tid];
                sw2[tid] = W2[(size_t)c * EDIM + n0 + tid];
            }
            __syncthreads();

            #pragma unroll
            for (int h = 0; h < 2; ++h) {
                uint4 aq[4];
                uint4 bq[8];
                #pragma unroll
                for (int rg = 0; rg < 4; ++rg) {
                    int row = wm * 32 + rg * 8 + (lane >> 2);
                    aq[rg] = *(const uint4*)&As[row * SROW + (lane & 3) * 8 + h * 4];
                }
                #pragma unroll
                for (int ni = 0; ni < 8; ++ni) {
                    int n = wn * 64 + ni * 8 + (lane >> 2);
                    bq[ni] = *(const uint4*)&Bs[n * SROW + (lane & 3) * 8 + h * 4];
                }
                #pragma unroll
                for (int sh = 0; sh < 2; ++sh) {
                    #pragma unroll
                    for (int mi = 0; mi < 2; ++mi) {
                        uint32_t a0 = sh ? aq[mi * 2].z     : aq[mi * 2].x;
                        uint32_t a2 = sh ? aq[mi * 2].w     : aq[mi * 2].y;
                        uint32_t a1 = sh ? aq[mi * 2 + 1].z : aq[mi * 2 + 1].x;
                        uint32_t a3 = sh ? aq[mi * 2 + 1].w : aq[mi * 2 + 1].y;
                        #pragma unroll
                        for (int ni = 0; ni < 8; ++ni) {
                            uint32_t bb0 = sh ? bq[ni].z : bq[ni].x;
                            uint32_t bb1 = sh ? bq[ni].w : bq[ni].y;
                            mma_tf32_frag(acc[mi][ni], a0, a1, a2, a3, bb0, bb1);
                        }
                    }
                }
            }
        }

        #pragma unroll
        for (int mi = 0; mi < 2; ++mi) {
            #pragma unroll
            for (int hi = 0; hi < 2; ++hi) {
                int row = wm * 32 + mi * 16 + hi * 8 + (lane >> 2);
                float rs = 0.0f;
                #pragma unroll
                for (int ni = 0; ni < 8; ++ni) {
                    float v0 = hi ? acc[mi][ni].z : acc[mi][ni].x;
                    float v1 = hi ? acc[mi][ni].w : acc[mi][ni].y;
                    int col = wn * 64 + ni * 8 + (lane & 3) * 2;
                    float g0 = gelu_erf(v0 + sb1[col]);
                    float g1 = gelu_erf(v1 + sb1[col + 1]);
                    rs += g0 * sw2[col] + g1 * sw2[col + 1];
                }
                rs += __shfl_xor_sync(0xffffffffu, rs, 1);
                rs += __shfl_xor_sync(0xffffffffu, rs, 2);
                if ((lane & 3) == 0) atomicAdd(&s_out[row], rs);
            }
        }
    }

    __syncthreads();
    if (tid < MT) {
        out[(size_t)b * (NCLS * CDF) + (size_t)c * CDF + tid] = s_out[tid] + b2[c];
    }
#else
    (void)x; (void)W1; (void)b1; (void)W2; (void)b2; (void)out;
#endif
}

// ======================================================================
// Host: launch both; exactly one variant has a non-empty body in the
// SASS image the loader picks. fb launched FIRST so ncu's "-s 5" lands
// on the tcgen05 kernel.
// ======================================================================
extern "C" void kernel_launch(void* const* d_in, const int* in_sizes, int n_in,
                              void* d_out, int out_size) {
    const float* x  = (const float*)d_in[0];
    const float* W1 = (const float*)d_in[1];
    const float* b1 = (const float*)d_in[2];
    const float* W2 = (const float*)d_in[3];
    const float* b2 = (const float*)d_in[4];
    float* out = (float*)d_out;

    static bool attr_set = false;
    if (!attr_set) {
        cudaFuncSetAttribute(mlp_head_tc, cudaFuncAttributeMaxDynamicSharedMemorySize, SMEM_TOTAL);
        attr_set = true;
    }

    dim3 grid(BATCH, NCLS);   // 1024 CTAs
    mlp_head_fb<<<grid, THREADS_FB>>>(x, W1, b1, W2, b2, out);
    mlp_head_tc<<<grid, THREADS_TC, SMEM_TOTAL>>>(x, W1, b1, W2, b2, out);
}

// round 5
// speedup vs baseline: 1.3296x; 1.3296x over previous
#include <cuda_runtime.h>
#include <cuda.h>
#include <cstdint>
#include <math.h>

#define BATCH   16
#define NCLS    64
#define CDF     128
#define EDIM    1024

// ===================== common helpers =====================
__device__ __forceinline__ uint32_t f2tf32(float f) {
    uint32_t u; asm("cvt.rna.tf32.f32 %0, %1;" : "=r"(u) : "f"(f)); return u;
}
__device__ __forceinline__ float gelu_erf(float v) {
    return 0.5f * v * (1.0f + erff(v * 0.7071067811865476f));
}

// Feature gate: tcgen05 only exists in arch-specific (sm_103a/sm_100a) passes.
#if defined(__CUDA_ARCH_FEAT_SM103_ALL) || defined(__CUDA_ARCH_FEAT_SM100_ALL) || defined(__CUDA_ARCH_FEAT_SM101_ALL)
#define TCGEN05_OK 1
#else
#define TCGEN05_OK 0
#endif

// 256MB scratch: W1 transposed + tf32-RNA rounded, layout [c][n][k]
__device__ float g_W1t[(size_t)NCLS * EDIM * EDIM];

// ======================================================================
// Kernel 0: W1 [c][k][n] -> g_W1t [c][n][k], tf32-RNA (32x32 smem transpose)
// ======================================================================
__global__ void __launch_bounds__(256)
w1_conv(const float* __restrict__ W1) {
    __shared__ float t[32][33];
    const int c  = blockIdx.z;
    const int k0 = blockIdx.x * 32;
    const int n0 = blockIdx.y * 32;
    const float* src = W1 + ((size_t)c << 20);
    float*       dst = g_W1t + ((size_t)c << 20);
    const int tx = threadIdx.x, ty = threadIdx.y;   // 32 x 8
    #pragma unroll
    for (int i = 0; i < 4; ++i)
        t[ty + i * 8][tx] = src[(size_t)(k0 + ty + i * 8) * EDIM + n0 + tx];
    __syncthreads();
    #pragma unroll
    for (int i = 0; i < 4; ++i) {
        float v = t[tx][ty + i * 8];   // = W1[c][k0+tx][n0+ty+i*8]
        dst[(size_t)(n0 + ty + i * 8) * EDIM + k0 + tx] = __uint_as_float(f2tf32(v));
    }
}

// ======================================================================
// Path A: tcgen05 tf32 warp-specialized kernel, B via TMA multicast
// ======================================================================
#define NCHUNK  256        // N columns per TMEM chunk (4 chunks total)
#define KT      32         // K per SMEM tile (4 tcgen05 K=8 steps)
#define NSTAGE  4
#define THREADS_TC 288     // warps 0-3 epilogue, 4-7 A-stagers, 8 MMA
#define CLUSTER 4
#define B_TILE_BYTES 32768u
#define B_SLICE_BYTES 8192u

#define OFF_TMEM   0
#define OFF_MB     8                    // per stage s: full @ 8+16s, empty @ 8+16s+8
#define OFF_CHK    72                   // chunk_done[2] @ 72+8p
#define OFF_EPI    88                   // epi_done[2]   @ 88+8p
#define OFF_SB1    128                  // float[2][256]
#define OFF_SW2    (128 + 2048)         // float[2][256]
#define OFF_TILE   8192
#define STAGE_BYTES 49152               // A 16KB + B 32KB, 1KB aligned
#define BTILE_OFF   16384
#define SMEM_TOTAL (OFF_TILE + NSTAGE * STAGE_BYTES)   // 204800

// idesc: kind::tf32, D=F32(1)@[4], atype=TF32(2)@[7], btype=TF32(2)@[10],
// N>>3 @[17], M>>4 @[24]
#define IDESC_TF32 ((1u<<4) | (2u<<7) | (2u<<10) | ((NCHUNK/8)<<17) | ((128/16)<<24))

#if TCGEN05_OK
__device__ __forceinline__ uint64_t make_desc(uint32_t addr) {
    return (uint64_t(2) << 61) | (uint64_t(1) << 46) | (uint64_t(64) << 32)
         | (uint64_t(1) << 16) | ((uint64_t)(addr >> 4) & 0x3FFF);
}
__device__ __forceinline__ uint32_t smem_u32(const void* p) {
    uint32_t a;
    asm("{ .reg .u64 t; cvta.to.shared.u64 t, %1; cvt.u32.u64 %0, t; }" : "=r"(a) : "l"(p));
    return a;
}
__device__ __forceinline__ void sts128(uint32_t a, uint32_t x, uint32_t y, uint32_t z, uint32_t w) {
    asm volatile("st.shared.v4.b32 [%0], {%1,%2,%3,%4};" :: "r"(a), "r"(x), "r"(y), "r"(z), "r"(w) : "memory");
}
__device__ __forceinline__ void mbar_init(uint32_t a, uint32_t cnt) {
    asm volatile("mbarrier.init.shared.b64 [%0], %1;" :: "r"(a), "r"(cnt) : "memory");
}
__device__ __forceinline__ void mbar_arrive(uint32_t a) {
    asm volatile("mbarrier.arrive.shared.b64 _, [%0];" :: "r"(a) : "memory");
}
__device__ __forceinline__ void mbar_wait(uint32_t a, uint32_t parity) {
    asm volatile(
        "{\n\t.reg .pred P;\n\t"
        "WL%=:\n\t"
        "mbarrier.try_wait.parity.acquire.cta.shared::cta.b64 P, [%0], %1, 0x989680;\n\t"
        "@P bra.uni WD%=;\n\t"
        "bra.uni WL%=;\n\t"
        "WD%=:\n\t}" :: "r"(a), "r"(parity) : "memory");
}
__device__ __forceinline__ void fence_async_proxy() {
    asm volatile("fence.proxy.async.shared::cta;" ::: "memory");
}
__device__ __forceinline__ void tc_commit(uint32_t mbar) {
    asm volatile("tcgen05.commit.cta_group::1.mbarrier::arrive::one.shared::cluster.b64 [%0];"
                 :: "r"(mbar) : "memory");
}
__device__ __forceinline__ void tc_commit_mc(uint32_t mbar, uint16_t mask) {
    asm volatile("tcgen05.commit.cta_group::1.mbarrier::arrive::one.shared::cluster.multicast::cluster.b64 [%0], %1;"
                 :: "r"(mbar), "h"(mask) : "memory");
}
__device__ __forceinline__ void mma_tf32_ss(uint32_t d, uint64_t ad, uint64_t bd,
                                            uint32_t idesc, uint32_t enable) {
    asm volatile(
        "{\n\t.reg .pred p;\n\t"
        "setp.ne.u32 p, %5, 0;\n\t"
        "tcgen05.mma.cta_group::1.kind::tf32 [%0], %1, %2, %3, {%4,%4,%4,%4}, p;\n\t}"
        :: "r"(d), "l"(ad), "l"(bd), "r"(idesc), "r"(0u), "r"(enable) : "memory");
}
#endif  // TCGEN05_OK

__global__ void __launch_bounds__(THREADS_TC, 1)
mlp_head_tc(const __grid_constant__ CUtensorMap tmapB,
            const float* __restrict__ x,
            const float* __restrict__ b1,
            const float* __restrict__ W2,
            const float* __restrict__ b2,
            float* __restrict__ out)
{
#if TCGEN05_OK
    extern __shared__ char smem[];
    const uint32_t sb = smem_u32(smem);

    const int tid  = threadIdx.x;
    const int warp = tid >> 5;
    const int lane = tid & 31;
    const int b    = blockIdx.x;
    const int c    = blockIdx.y;
    uint32_t rank;
    asm("mov.u32 %0, %%cluster_ctarank;" : "=r"(rank));

    const float* Abase = x + ((size_t)b * (NCLS * CDF) + (size_t)c * CDF) * EDIM;

    float* sb1s = (float*)(smem + OFF_SB1);
    float* sw2s = (float*)(smem + OFF_SW2);

    if (warp == 8) {
        asm volatile("tcgen05.alloc.cta_group::1.sync.aligned.shared::cta.b32 [%0], %1;"
                     :: "r"(sb + OFF_TMEM), "r"(512u) : "memory");
    }
    if (tid == 0) {
        #pragma unroll
        for (int s = 0; s < NSTAGE; ++s) {
            mbar_init(sb + OFF_MB + s * 16,     129);  // full: 128 stagers + 1 expect_tx arrive
            mbar_init(sb + OFF_MB + s * 16 + 8, CLUSTER); // empty: 4 multicast commits
        }
        mbar_init(sb + OFF_CHK + 0, 1);   mbar_init(sb + OFF_CHK + 8, 1);
        mbar_init(sb + OFF_EPI + 0, 128); mbar_init(sb + OFF_EPI + 8, 128);
    }
    __syncthreads();
    // all cluster CTAs' barriers must be live before any multicast TMA / commit
    asm volatile("barrier.cluster.arrive.aligned;" ::: "memory");
    asm volatile("barrier.cluster.wait.aligned;" ::: "memory");

    uint32_t tmem;
    asm volatile("ld.shared.b32 %0, [%1];" : "=r"(tmem) : "r"(sb + OFF_TMEM));

    if (warp >= 4 && warp < 8) {
        // ===== PRODUCERS (warps 4-7): A via LDG+cvt+STS, B via TMA multicast =====
        const int local = tid - 128;
        const int q  = local & 7;    // 16B quad within 128B row (A)
        const int r8 = local >> 3;   // 0..15
        const int NTILES = 4 * (EDIM / KT);   // 128

        float4 abuf[8];
        auto load_a = [&](int g) {
            const int gi = (g < NTILES) ? g : (NTILES - 1);
            const int k0 = (gi & 31) * KT;
            const float* Ak = Abase + k0 + (size_t)r8 * EDIM + q * 4;
            #pragma unroll
            for (int ps = 0; ps < 8; ++ps)
                abuf[ps] = *(const float4*)(Ak + (size_t)ps * 16 * EDIM);
        };

        load_a(0);
        for (int g = 0; g < NTILES; ++g) {
            const int s = g & (NSTAGE - 1);
            const int r = g >> 2;                      // ring round
            const uint32_t fullb  = sb + OFF_MB + s * 16;
            const uint32_t emptyb = fullb + 8;
            mbar_wait(emptyb, (r & 1) ^ 1);            // all 4 CTAs done with stage s

            const uint32_t a_sm = sb + OFF_TILE + s * STAGE_BYTES;
            const uint32_t b_sm = a_sm + BTILE_OFF;

            // one thread: expect full B bytes locally, TMA-multicast my 64-row slice
            if (local == 0) {
                asm volatile("mbarrier.arrive.expect_tx.shared.b64 _, [%0], %1;"
                             :: "r"(fullb), "r"(B_TILE_BYTES) : "memory");
                const int k0 = (g & 31) * KT;
                const int ng = (g >> 5) * NCHUNK + (int)rank * 64;
                asm volatile(
                    "cp.async.bulk.tensor.3d.shared::cluster.global.tile"
                    ".mbarrier::complete_tx::bytes.multicast::cluster "
                    "[%0], [%1, {%2, %3, %4}], [%5], %6;"
                    :: "r"(b_sm + rank * B_SLICE_BYTES), "l"(&tmapB),
                       "r"(k0), "r"(ng), "r"(c), "r"(fullb),
                       "h"((uint16_t)0xF) : "memory");
            }

            // ---- A tile: 128 rows x 32 k (tf32-RNA, SW128) ----
            #pragma unroll
            for (int ps = 0; ps < 8; ++ps) {
                const int row = ps * 16 + r8;
                uint32_t off = row * 128 + q * 16;
                off ^= (off >> 3) & 0x70;
                sts128(a_sm + off, f2tf32(abuf[ps].x), f2tf32(abuf[ps].y),
                       f2tf32(abuf[ps].z), f2tf32(abuf[ps].w));
            }
            fence_async_proxy();
            mbar_arrive(fullb);
            load_a(g + 1);                 // overlap next A tile's GMEM latency
        }
    } else if (warp == 8) {
        // ================= MMA ISSUE (warp 8, lane 0) =================
        if (lane == 0) {
            uint64_t ad[NSTAGE], bd[NSTAGE];
            #pragma unroll
            for (int s = 0; s < NSTAGE; ++s) {
                ad[s] = make_desc(sb + OFF_TILE + s * STAGE_BYTES);
                bd[s] = make_desc(sb + OFF_TILE + s * STAGE_BYTES + BTILE_OFF);
            }
            int g = 0;
            for (int ci = 0; ci < 4; ++ci) {
                const int p = ci & 1;
                if (ci >= 2) {
                    mbar_wait(sb + OFF_EPI + p * 8, 0);   // D region free
                    asm volatile("tcgen05.fence::after_thread_sync;" ::: "memory");
                }
                const uint32_t dt = tmem + p * NCHUNK;
                for (int kt = 0; kt < 32; ++kt, ++g) {
                    const int s = g & (NSTAGE - 1);
                    const int r = g >> 2;
                    mbar_wait(sb + OFF_MB + s * 16, r & 1);   // full
                    #pragma unroll
                    for (int j = 0; j < 4; ++j) {
                        mma_tf32_ss(dt, ad[s] + j * 2, bd[s] + j * 2,
                                    IDESC_TF32, (kt > 0 || j > 0) ? 1u : 0u);
                    }
                    // stage empty: arrive on ALL cluster CTAs' empty barriers
                    tc_commit_mc(sb + OFF_MB + s * 16 + 8, (uint16_t)0xF);
                }
                tc_commit(sb + OFF_CHK + p * 8);              // local chunk_done
            }
        }
    } else {
        // ================= EPILOGUE (warps 0-3, 128 threads) =================
        float accum = 0.0f;
        for (int ci = 0; ci < 4; ++ci) {
            const int p = ci & 1;
            asm volatile("bar.sync 1, 128;" ::: "memory");
            sb1s[p * 256 + 2 * tid]     = b1[(size_t)c * EDIM + ci * NCHUNK + 2 * tid];
            sb1s[p * 256 + 2 * tid + 1] = b1[(size_t)c * EDIM + ci * NCHUNK + 2 * tid + 1];
            sw2s[p * 256 + 2 * tid]     = W2[(size_t)c * EDIM + ci * NCHUNK + 2 * tid];
            sw2s[p * 256 + 2 * tid + 1] = W2[(size_t)c * EDIM + ci * NCHUNK + 2 * tid + 1];
            asm volatile("bar.sync 1, 128;" ::: "memory");

            mbar_wait(sb + OFF_CHK + p * 8, (ci >> 1) & 1);
            asm volatile("tcgen05.fence::after_thread_sync;" ::: "memory");

            #pragma unroll
            for (int blk = 0; blk < NCHUNK / 32; ++blk) {
                uint32_t rg[32];
                asm volatile(
                    "tcgen05.ld.sync.aligned.32x32b.x32.b32 "
                    "{%0,%1,%2,%3,%4,%5,%6,%7,%8,%9,%10,%11,%12,%13,%14,%15,"
                    "%16,%17,%18,%19,%20,%21,%22,%23,%24,%25,%26,%27,%28,%29,%30,%31}, [%32];"
                    : "=r"(rg[0]),"=r"(rg[1]),"=r"(rg[2]),"=r"(rg[3]),"=r"(rg[4]),"=r"(rg[5]),
                      "=r"(rg[6]),"=r"(rg[7]),"=r"(rg[8]),"=r"(rg[9]),"=r"(rg[10]),"=r"(rg[11]),
                      "=r"(rg[12]),"=r"(rg[13]),"=r"(rg[14]),"=r"(rg[15]),"=r"(rg[16]),"=r"(rg[17]),
                      "=r"(rg[18]),"=r"(rg[19]),"=r"(rg[20]),"=r"(rg[21]),"=r"(rg[22]),"=r"(rg[23]),
                      "=r"(rg[24]),"=r"(rg[25]),"=r"(rg[26]),"=r"(rg[27]),"=r"(rg[28]),"=r"(rg[29]),
                      "=r"(rg[30]),"=r"(rg[31])
                    : "r"(tmem + p * NCHUNK + blk * 32));
                asm volatile("tcgen05.wait::ld.sync.aligned;" ::: "memory");
                #pragma unroll
                for (int j = 0; j < 32; ++j) {
                    const int col = p * 256 + blk * 32 + j;
                    float v = __uint_as_float(rg[j]) + sb1s[col];
                    accum += gelu_erf(v) * sw2s[col];
                }
            }
            asm volatile("tcgen05.fence::before_thread_sync;" ::: "memory");
            mbar_arrive(sb + OFF_EPI + p * 8);
        }
        const int row = warp * 32 + lane;
        out[(size_t)b * (NCLS * CDF) + (size_t)c * CDF + row] = accum + b2[c];
    }

    __syncthreads();
    if (warp == 8) {
        asm volatile("tcgen05.relinquish_alloc_permit.cta_group::1.sync.aligned;" ::: "memory");
        asm volatile("tcgen05.dealloc.cta_group::1.sync.aligned.b32 %0, %1;" :: "r"(tmem), "r"(512u));
    }
    // no CTA may exit while a peer's multicast into this CTA's smem is in flight
    asm volatile("barrier.cluster.arrive.aligned;" ::: "memory");
    asm volatile("barrier.cluster.wait.aligned;" ::: "memory");
#else
    (void)tmapB; (void)x; (void)b1; (void)W2; (void)b2; (void)out;
#endif
}

// ======================================================================
// Path B: fallback mma.sync tf32 kernel (active only on non-'a' passes)
// ======================================================================
#define MT      128
#define NT      128
#define KTF     32
#define THREADS_FB 256
#define SROW    36

#if !TCGEN05_OK
__device__ __forceinline__ void mma_tf32_frag(float4& d,
                                              uint32_t a0, uint32_t a1, uint32_t a2, uint32_t a3,
                                              uint32_t b0, uint32_t b1) {
    asm volatile(
        "mma.sync.aligned.m16n8k8.row.col.f32.tf32.tf32.f32 "
        "{%0,%1,%2,%3}, {%4,%5,%6,%7}, {%8,%9}, {%0,%1,%2,%3};\n"
        : "+f"(d.x), "+f"(d.y), "+f"(d.z), "+f"(d.w)
        : "r"(a0), "r"(a1), "r"(a2), "r"(a3), "r"(b0), "r"(b1));
}
#endif

__global__ void __launch_bounds__(THREADS_FB, 2)
mlp_head_fb(const float* __restrict__ x,
            const float* __restrict__ W1,
            const float* __restrict__ b1,
            const float* __restrict__ W2,
            const float* __restrict__ b2,
            float* __restrict__ out)
{
#if !TCGEN05_OK
    __shared__ uint32_t As[MT * SROW];
    __shared__ uint32_t Bs[NT * SROW];
    __shared__ float sb1[NT];
    __shared__ float sw2[NT];
    __shared__ float s_out[MT];

    const int b    = blockIdx.x;
    const int c    = blockIdx.y;
    const int tid  = threadIdx.x;
    const int lane = tid & 31;
    const int warp = tid >> 5;
    const int wm   = warp >> 1;
    const int wn   = warp & 1;

    const float* Abase = x  + ((size_t)b * (NCLS * CDF) + (size_t)c * CDF) * EDIM;
    const float* W1c   = W1 + (size_t)c * EDIM * EDIM;

    if (tid < MT) s_out[tid] = 0.0f;

    for (int n0 = 0; n0 < EDIM; n0 += NT) {
        float4 acc[2][8];
        #pragma unroll
        for (int mi = 0; mi < 2; ++mi)
            #pragma unroll
            for (int ni = 0; ni < 8; ++ni)
                acc[mi][ni] = make_float4(0.f, 0.f, 0.f, 0.f);

        for (int k0 = 0; k0 < EDIM; k0 += KTF) {
            __syncthreads();
            {
                const float* Ak = Abase + k0;
                const int kq = tid & 7;
                const int r0 = tid >> 3;
                #pragma unroll
                for (int it = 0; it < 4; ++it) {
                    int r = r0 + it * 32;
                    float4 v = *(const float4*)(Ak + (size_t)r * EDIM + kq * 4);
                    uint32_t* dst = &As[r * SROW + kq];
                    dst[0]  = f2tf32(v.x);
                    dst[8]  = f2tf32(v.y);
                    dst[16] = f2tf32(v.z);
                    dst[24] = f2tf32(v.w);
                }
            }
            {
                const int n  = tid & 127;
                const int kh = tid >> 7;
                const float* Bp = W1c + (size_t)k0 * EDIM + n0 + n;
                #pragma unroll
                for (int kk = 0; kk < 4; ++kk) {
                    int kbase = kk * 8 + kh * 4;
                    #pragma unroll
                    for (int i = 0; i < 4; ++i) {
                        float v = Bp[(size_t)(kbase + i) * EDIM];
                        Bs[n * SROW + i * 8 + kk * 2 + kh] = f2tf32(v);
                    }
                }
            }
            if (k0 == 0 && tid < NT) {
                sb1[tid] = b1[(size_t)c * EDIM + n0 + tid];
                sw2[tid] = W2[(size_t)c * EDIM + n0 + tid];
            }
            __syncthreads();

            #pragma unroll
            for (int h = 0; h < 2; ++h) {
                uint4 aq[4];
                uint4 bq[8];
                #pragma unroll
                for (int rg = 0; rg < 4; ++rg) {
                    int row = wm * 32 + rg * 8 + (lane >> 2);
                    aq[rg] = *(const uint4*)&As[row * SROW + (lane & 3) * 8 + h * 4];
                }
                #pragma unroll
                for (int ni = 0; ni < 8; ++ni) {
                    int n = wn * 64 + ni * 8 + (lane >> 2);
                    bq[ni] = *(const uint4*)&Bs[n * SROW + (lane & 3) * 8 + h * 4];
                }
                #pragma unroll
                for (int sh = 0; sh < 2; ++sh) {
                    #pragma unroll
                    for (int mi = 0; mi < 2; ++mi) {
                        uint32_t a0 = sh ? aq[mi * 2].z     : aq[mi * 2].x;
                        uint32_t a2 = sh ? aq[mi * 2].w     : aq[mi * 2].y;
                        uint32_t a1 = sh ? aq[mi * 2 + 1].z : aq[mi * 2 + 1].x;
                        uint32_t a3 = sh ? aq[mi * 2 + 1].w : aq[mi * 2 + 1].y;
                        #pragma unroll
                        for (int ni = 0; ni < 8; ++ni) {
                            uint32_t bb0 = sh ? bq[ni].z : bq[ni].x;
                            uint32_t bb1 = sh ? bq[ni].w : bq[ni].y;
                            mma_tf32_frag(acc[mi][ni], a0, a1, a2, a3, bb0, bb1);
                        }
                    }
                }
            }
        }

        #pragma unroll
        for (int mi = 0; mi < 2; ++mi) {
            #pragma unroll
            for (int hi = 0; hi < 2; ++hi) {
                int row = wm * 32 + mi * 16 + hi * 8 + (lane >> 2);
                float rs = 0.0f;
                #pragma unroll
                for (int ni = 0; ni < 8; ++ni) {
                    float v0 = hi ? acc[mi][ni].z : acc[mi][ni].x;
                    float v1 = hi ? acc[mi][ni].w : acc[mi][ni].y;
                    int col = wn * 64 + ni * 8 + (lane & 3) * 2;
                    float g0 = gelu_erf(v0 + sb1[col]);
                    float g1 = gelu_erf(v1 + sb1[col + 1]);
                    rs += g0 * sw2[col] + g1 * sw2[col + 1];
                }
                rs += __shfl_xor_sync(0xffffffffu, rs, 1);
                rs += __shfl_xor_sync(0xffffffffu, rs, 2);
                if ((lane & 3) == 0) atomicAdd(&s_out[row], rs);
            }
        }
    }

    __syncthreads();
    if (tid < MT) {
        out[(size_t)b * (NCLS * CDF) + (size_t)c * CDF + tid] = s_out[tid] + b2[c];
    }
#else
    (void)x; (void)W1; (void)b1; (void)W2; (void)b2; (void)out;
#endif
}

// ======================================================================
// Host
// ======================================================================
static void encode_tmap_b(CUtensorMap* tm, void* base) {
    typedef CUresult (*EncodeFn)(CUtensorMap*, CUtensorMapDataType, cuuint32_t, void*,
                                 const cuuint64_t*, const cuuint64_t*, const cuuint32_t*,
                                 const cuuint32_t*, CUtensorMapInterleave, CUtensorMapSwizzle,
                                 CUtensorMapL2promotion, CUtensorMapFloatOOBfill);
    EncodeFn fn = nullptr;
    cudaDriverEntryPointQueryResult qr;
#if CUDART_VERSION >= 12050
    cudaGetDriverEntryPointByVersion("cuTensorMapEncodeTiled", (void**)&fn, 12000,
                                     cudaEnableDefault, &qr);
#else
    cudaGetDriverEntryPoint("cuTensorMapEncodeTiled", (void**)&fn, cudaEnableDefault, &qr);
#endif
    if (!fn) return;
    cuuint64_t dims[3]    = {EDIM, EDIM, NCLS};                      // [k, n, c]
    cuuint64_t strides[2] = {EDIM * 4ull, (cuuint64_t)EDIM * EDIM * 4ull};
    cuuint32_t box[3]     = {KT, 64, 1};                             // 32k x 64n slice
    cuuint32_t estr[3]    = {1, 1, 1};
    fn(tm, CU_TENSOR_MAP_DATA_TYPE_FLOAT32, 3, base, dims, strides, box, estr,
       CU_TENSOR_MAP_INTERLEAVE_NONE, CU_TENSOR_MAP_SWIZZLE_128B,
       CU_TENSOR_MAP_L2_PROMOTION_L2_128B, CU_TENSOR_MAP_FLOAT_OOB_FILL_NONE);
}

extern "C" void kernel_launch(void* const* d_in, const int* in_sizes, int n_in,
                              void* d_out, int out_size) {
    const float* x  = (const float*)d_in[0];
    const float* W1 = (const float*)d_in[1];
    const float* b1 = (const float*)d_in[2];
    const float* W2 = (const float*)d_in[3];
    const float* b2 = (const float*)d_in[4];
    float* out = (float*)d_out;

    void* w1t_ptr = nullptr;
    cudaGetSymbolAddress(&w1t_ptr, g_W1t);
    CUtensorMap tm;
    encode_tmap_b(&tm, w1t_ptr);

    cudaFuncSetAttribute(mlp_head_tc, cudaFuncAttributeMaxDynamicSharedMemorySize, SMEM_TOTAL);

    dim3 grid(BATCH, NCLS);

    // fb first (no-op on sm_103a image), then conversion, then cluster GEMM
    mlp_head_fb<<<grid, THREADS_FB>>>(x, W1, b1, W2, b2, out);
    w1_conv<<<dim3(EDIM / 32, EDIM / 32, NCLS), dim3(32, 8)>>>(W1);

    cudaLaunchConfig_t cfg = {};
    cfg.gridDim  = grid;
    cfg.blockDim = dim3(THREADS_TC, 1, 1);
    cfg.dynamicSmemBytes = SMEM_TOTAL;
    cfg.stream = 0;
    cudaLaunchAttribute attrs[1];
    attrs[0].id = cudaLaunchAttributeClusterDimension;
    attrs[0].val.clusterDim = {CLUSTER, 1, 1};   // 4 batch-CTAs share one class's W1
    cfg.attrs = attrs;
    cfg.numAttrs = 1;
    cudaLaunchKernelEx(&cfg, mlp_head_tc, tm, x, b1, W2, b2, out);
}

// round 6
// speedup vs baseline: 1.4764x; 1.1104x over previous
#include <cuda_runtime.h>
#include <cuda.h>
#include <cstdint>
#include <math.h>

#define BATCH   16
#define NCLS    64
#define CDF     128
#define EDIM    1024

// ===================== common helpers =====================
__device__ __forceinline__ uint32_t f2tf32(float f) {
    uint32_t u; asm("cvt.rna.tf32.f32 %0, %1;" : "=r"(u) : "f"(f)); return u;
}
__device__ __forceinline__ float gelu_erf(float v) {
    return 0.5f * v * (1.0f + erff(v * 0.7071067811865476f));
}

// Feature gate: tcgen05 only exists in arch-specific (sm_103a/sm_100a) passes.
#if defined(__CUDA_ARCH_FEAT_SM103_ALL) || defined(__CUDA_ARCH_FEAT_SM100_ALL) || defined(__CUDA_ARCH_FEAT_SM101_ALL)
#define TCGEN05_OK 1
#else
#define TCGEN05_OK 0
#endif

// 256MB scratch: W1 transposed + tf32-RNA rounded, layout [c][n][k]
__device__ float g_W1t[(size_t)NCLS * EDIM * EDIM];

// ======================================================================
// Kernel 0: W1 [c][k][n] -> g_W1t [c][n][k], tf32-RNA (32x32 smem transpose)
// ======================================================================
__global__ void __launch_bounds__(256)
w1_conv(const float* __restrict__ W1) {
    __shared__ float t[32][33];
    const int c  = blockIdx.z;
    const int k0 = blockIdx.x * 32;
    const int n0 = blockIdx.y * 32;
    const float* src = W1 + ((size_t)c << 20);
    float*       dst = g_W1t + ((size_t)c << 20);
    const int tx = threadIdx.x, ty = threadIdx.y;   // 32 x 8
    #pragma unroll
    for (int i = 0; i < 4; ++i)
        t[ty + i * 8][tx] = src[(size_t)(k0 + ty + i * 8) * EDIM + n0 + tx];
    __syncthreads();
    #pragma unroll
    for (int i = 0; i < 4; ++i) {
        float v = t[tx][ty + i * 8];   // = W1[c][k0+tx][n0+ty+i*8]
        dst[(size_t)(n0 + ty + i * 8) * EDIM + k0 + tx] = __uint_as_float(f2tf32(v));
    }
}

// ======================================================================
// tcgen05 tf32 warp-specialized kernel, B via TMA multicast, KT=64
// ======================================================================
#define NCHUNK  256        // N columns per TMEM chunk (4 chunks total)
#define KT      64         // K per stage (8 tcgen05 K=8 dispatches)
#define NSTAGE  2
#define THREADS_TC 288     // warps 0-3 epilogue, 4-7 A-stagers, 8 MMA
#define CLUSTER 4
#define B_TILE_BYTES 65536u   // 256n x 64k x 4B per stage (full, after multicast)
#define B_SUB_BYTES  32768u   // one 32-k half of B
#define B_SLICE_BYTES 8192u   // one rank's [32k x 64n] TMA box
#define A_SUB_BYTES  16384u   // one 32-k half of A (128 rows x 128B)

#define OFF_TMEM   0
#define OFF_MB     8                    // per stage s: full @ 8+16s, empty @ 8+16s+8
#define OFF_CHK    72                   // chunk_done[2] @ 72+8p
#define OFF_EPI    88                   // epi_done[2]   @ 88+8p
#define OFF_SB1    128                  // float[1024]
#define OFF_SW2    (128 + 4096)         // float[1024]
#define OFF_TILE   9216                 // 1KB aligned
#define STAGE_BYTES 98304               // A 32KB (2 subs) + B 64KB (2 subs)
#define BTILE_OFF   32768
#define SMEM_TOTAL (OFF_TILE + NSTAGE * STAGE_BYTES)   // 205824

// idesc: kind::tf32, D=F32(1)@[4], atype=TF32(2)@[7], btype=TF32(2)@[10],
// N>>3 @[17], M>>4 @[24]
#define IDESC_TF32 ((1u<<4) | (2u<<7) | (2u<<10) | ((NCHUNK/8)<<17) | ((128/16)<<24))

#if TCGEN05_OK
__device__ __forceinline__ uint64_t make_desc(uint32_t addr) {
    return (uint64_t(2) << 61) | (uint64_t(1) << 46) | (uint64_t(64) << 32)
         | (uint64_t(1) << 16) | ((uint64_t)(addr >> 4) & 0x3FFF);
}
__device__ __forceinline__ uint32_t smem_u32(const void* p) {
    uint32_t a;
    asm("{ .reg .u64 t; cvta.to.shared.u64 t, %1; cvt.u32.u64 %0, t; }" : "=r"(a) : "l"(p));
    return a;
}
__device__ __forceinline__ void sts128(uint32_t a, uint32_t x, uint32_t y, uint32_t z, uint32_t w) {
    asm volatile("st.shared.v4.b32 [%0], {%1,%2,%3,%4};" :: "r"(a), "r"(x), "r"(y), "r"(z), "r"(w) : "memory");
}
__device__ __forceinline__ void mbar_init(uint32_t a, uint32_t cnt) {
    asm volatile("mbarrier.init.shared.b64 [%0], %1;" :: "r"(a), "r"(cnt) : "memory");
}
__device__ __forceinline__ void mbar_arrive(uint32_t a) {
    asm volatile("mbarrier.arrive.shared.b64 _, [%0];" :: "r"(a) : "memory");
}
__device__ __forceinline__ void mbar_wait(uint32_t a, uint32_t parity) {
    asm volatile(
        "{\n\t.reg .pred P;\n\t"
        "WL%=:\n\t"
        "mbarrier.try_wait.parity.acquire.cta.shared::cta.b64 P, [%0], %1, 0x989680;\n\t"
        "@P bra.uni WD%=;\n\t"
        "bra.uni WL%=;\n\t"
        "WD%=:\n\t}" :: "r"(a), "r"(parity) : "memory");
}
__device__ __forceinline__ void fence_async_proxy() {
    asm volatile("fence.proxy.async.shared::cta;" ::: "memory");
}
__device__ __forceinline__ void tc_commit(uint32_t mbar) {
    asm volatile("tcgen05.commit.cta_group::1.mbarrier::arrive::one.shared::cluster.b64 [%0];"
                 :: "r"(mbar) : "memory");
}
__device__ __forceinline__ void tc_commit_mc(uint32_t mbar, uint16_t mask) {
    asm volatile("tcgen05.commit.cta_group::1.mbarrier::arrive::one.shared::cluster.multicast::cluster.b64 [%0], %1;"
                 :: "r"(mbar), "h"(mask) : "memory");
}
__device__ __forceinline__ void mma_tf32_ss(uint32_t d, uint64_t ad, uint64_t bd,
                                            uint32_t idesc, uint32_t enable) {
    asm volatile(
        "{\n\t.reg .pred p;\n\t"
        "setp.ne.u32 p, %5, 0;\n\t"
        "tcgen05.mma.cta_group::1.kind::tf32 [%0], %1, %2, %3, {%4,%4,%4,%4}, p;\n\t}"
        :: "r"(d), "l"(ad), "l"(bd), "r"(idesc), "r"(0u), "r"(enable) : "memory");
}
#endif  // TCGEN05_OK

__global__ void __launch_bounds__(THREADS_TC, 1)
mlp_head_tc(const __grid_constant__ CUtensorMap tmapB,
            const float* __restrict__ x,
            const float* __restrict__ b1,
            const float* __restrict__ W2,
            const float* __restrict__ b2,
            float* __restrict__ out)
{
#if TCGEN05_OK
    extern __shared__ char smem[];
    const uint32_t sb = smem_u32(smem);

    const int tid  = threadIdx.x;
    const int warp = tid >> 5;
    const int lane = tid & 31;
    const int b    = blockIdx.x;
    const int c    = blockIdx.y;
    uint32_t rank;
    asm("mov.u32 %0, %%cluster_ctarank;" : "=r"(rank));

    const float* Abase = x + ((size_t)b * (NCLS * CDF) + (size_t)c * CDF) * EDIM;

    float* sb1s = (float*)(smem + OFF_SB1);
    float* sw2s = (float*)(smem + OFF_SW2);

    if (warp == 8) {
        asm volatile("tcgen05.alloc.cta_group::1.sync.aligned.shared::cta.b32 [%0], %1;"
                     :: "r"(sb + OFF_TMEM), "r"(512u) : "memory");
    }
    if (tid == 0) {
        #pragma unroll
        for (int s = 0; s < NSTAGE; ++s) {
            mbar_init(sb + OFF_MB + s * 16,     129);     // full: 128 stagers + 1 expect_tx
            mbar_init(sb + OFF_MB + s * 16 + 8, CLUSTER); // empty: 4 multicast commits
        }
        mbar_init(sb + OFF_CHK + 0, 1);   mbar_init(sb + OFF_CHK + 8, 1);
        mbar_init(sb + OFF_EPI + 0, 128); mbar_init(sb + OFF_EPI + 8, 128);
    }
    __syncthreads();
    // all cluster CTAs' barriers must be live before any multicast TMA / commit
    asm volatile("barrier.cluster.arrive.aligned;" ::: "memory");
    asm volatile("barrier.cluster.wait.aligned;" ::: "memory");

    uint32_t tmem;
    asm volatile("ld.shared.b32 %0, [%1];" : "=r"(tmem) : "r"(sb + OFF_TMEM));

    if (warp >= 4 && warp < 8) {
        // ===== PRODUCERS (warps 4-7): A via LDG+cvt+STS, B via TMA multicast =====
        const int local = tid - 128;
        const int q  = local & 7;    // 16B quad within 128B row
        const int r8 = local >> 3;   // 0..15
        const int NTILES = 4 * (EDIM / KT);   // 64 stages total

        float4 abuf[16];   // 2 k-subs x 8 row-passes
        auto load_a = [&](int g) {
            const int gi = (g < NTILES) ? g : (NTILES - 1);
            const int k0 = (gi & 15) * KT;
            #pragma unroll
            for (int sub = 0; sub < 2; ++sub) {
                const float* Ak = Abase + k0 + sub * 32 + (size_t)r8 * EDIM + q * 4;
                #pragma unroll
                for (int ps = 0; ps < 8; ++ps)
                    abuf[sub * 8 + ps] = *(const float4*)(Ak + (size_t)ps * 16 * EDIM);
            }
        };

        load_a(0);
        for (int g = 0; g < NTILES; ++g) {
            const int s = g & (NSTAGE - 1);
            const int r = g >> 1;                      // ring round
            const uint32_t fullb  = sb + OFF_MB + s * 16;
            const uint32_t emptyb = fullb + 8;
            mbar_wait(emptyb, (r & 1) ^ 1);            // all 4 CTAs done with stage s

            const uint32_t a_sm = sb + OFF_TILE + s * STAGE_BYTES;
            const uint32_t b_sm = a_sm + BTILE_OFF;

            // one thread: expect full 64KB B, TMA-multicast my two 8KB slices
            if (local == 0) {
                asm volatile("mbarrier.arrive.expect_tx.shared.b64 _, [%0], %1;"
                             :: "r"(fullb), "r"(B_TILE_BYTES) : "memory");
                const int k0 = (g & 15) * KT;
                const int ng = (g >> 4) * NCHUNK + (int)rank * 64;
                #pragma unroll
                for (int sub = 0; sub < 2; ++sub) {
                    asm volatile(
                        "cp.async.bulk.tensor.3d.shared::cluster.global.tile"
                        ".mbarrier::complete_tx::bytes.multicast::cluster "
                        "[%0], [%1, {%2, %3, %4}], [%5], %6;"
                        :: "r"(b_sm + sub * B_SUB_BYTES + rank * B_SLICE_BYTES), "l"(&tmapB),
                           "r"(k0 + sub * 32), "r"(ng), "r"(c), "r"(fullb),
                           "h"((uint16_t)0xF) : "memory");
                }
            }

            // ---- A tile: 2 subs x (128 rows x 32 k), tf32-RNA, SW128 ----
            #pragma unroll
            for (int sub = 0; sub < 2; ++sub) {
                #pragma unroll
                for (int ps = 0; ps < 8; ++ps) {
                    const int row = ps * 16 + r8;
                    uint32_t off = row * 128 + q * 16;
                    off ^= (off >> 3) & 0x70;
                    const float4 v = abuf[sub * 8 + ps];
                    sts128(a_sm + sub * A_SUB_BYTES + off,
                           f2tf32(v.x), f2tf32(v.y), f2tf32(v.z), f2tf32(v.w));
                }
            }
            fence_async_proxy();
            mbar_arrive(fullb);
            load_a(g + 1);                 // overlap next A tile's GMEM latency
        }
    } else if (warp == 8) {
        // ================= MMA ISSUE (warp 8, lane 0) =================
        if (lane == 0) {
            uint64_t ad[NSTAGE], bd[NSTAGE];
            #pragma unroll
            for (int s = 0; s < NSTAGE; ++s) {
                ad[s] = make_desc(sb + OFF_TILE + s * STAGE_BYTES);
                bd[s] = make_desc(sb + OFF_TILE + s * STAGE_BYTES + BTILE_OFF);
            }
            int g = 0;
            for (int ci = 0; ci < 4; ++ci) {
                const int p = ci & 1;
                if (ci >= 2) {
                    mbar_wait(sb + OFF_EPI + p * 8, 0);   // D region free
                    asm volatile("tcgen05.fence::after_thread_sync;" ::: "memory");
                }
                const uint32_t dt = tmem + p * NCHUNK;
                for (int kt = 0; kt < 16; ++kt, ++g) {
                    const int s = g & (NSTAGE - 1);
                    const int r = g >> 1;
                    mbar_wait(sb + OFF_MB + s * 16, r & 1);   // full
                    #pragma unroll
                    for (int j = 0; j < 8; ++j) {
                        const int sub = j >> 2;
                        const int jj  = j & 3;
                        mma_tf32_ss(dt,
                                    ad[s] + sub * (A_SUB_BYTES / 16) + jj * 2,
                                    bd[s] + sub * (B_SUB_BYTES / 16) + jj * 2,
                                    IDESC_TF32, (kt > 0 || j > 0) ? 1u : 0u);
                    }
                    // stage empty: arrive on ALL cluster CTAs' empty barriers
                    tc_commit_mc(sb + OFF_MB + s * 16 + 8, (uint16_t)0xF);
                }
                tc_commit(sb + OFF_CHK + p * 8);              // local chunk_done
            }
        }
    } else {
        // ================= EPILOGUE (warps 0-3, 128 threads) =================
        // preload all 1024 b1/W2 once
        #pragma unroll
        for (int i = 0; i < 8; ++i) {
            sb1s[tid + i * 128] = b1[(size_t)c * EDIM + tid + i * 128];
            sw2s[tid + i * 128] = W2[(size_t)c * EDIM + tid + i * 128];
        }
        asm volatile("bar.sync 1, 128;" ::: "memory");

        float accum = 0.0f;
        for (int ci = 0; ci < 4; ++ci) {
            const int p = ci & 1;
            mbar_wait(sb + OFF_CHK + p * 8, (ci >> 1) & 1);
            asm volatile("tcgen05.fence::after_thread_sync;" ::: "memory");

            #pragma unroll
            for (int blk = 0; blk < NCHUNK / 32; ++blk) {
                uint32_t rg[32];
                asm volatile(
                    "tcgen05.ld.sync.aligned.32x32b.x32.b32 "
                    "{%0,%1,%2,%3,%4,%5,%6,%7,%8,%9,%10,%11,%12,%13,%14,%15,"
                    "%16,%17,%18,%19,%20,%21,%22,%23,%24,%25,%26,%27,%28,%29,%30,%31}, [%32];"
                    : "=r"(rg[0]),"=r"(rg[1]),"=r"(rg[2]),"=r"(rg[3]),"=r"(rg[4]),"=r"(rg[5]),
                      "=r"(rg[6]),"=r"(rg[7]),"=r"(rg[8]),"=r"(rg[9]),"=r"(rg[10]),"=r"(rg[11]),
                      "=r"(rg[12]),"=r"(rg[13]),"=r"(rg[14]),"=r"(rg[15]),"=r"(rg[16]),"=r"(rg[17]),
                      "=r"(rg[18]),"=r"(rg[19]),"=r"(rg[20]),"=r"(rg[21]),"=r"(rg[22]),"=r"(rg[23]),
                      "=r"(rg[24]),"=r"(rg[25]),"=r"(rg[26]),"=r"(rg[27]),"=r"(rg[28]),"=r"(rg[29]),
                      "=r"(rg[30]),"=r"(rg[31])
                    : "r"(tmem + p * NCHUNK + blk * 32));
                asm volatile("tcgen05.wait::ld.sync.aligned;" ::: "memory");
                #pragma unroll
                for (int j = 0; j < 32; ++j) {
                    const int col = ci * NCHUNK + blk * 32 + j;
                    float v = __uint_as_float(rg[j]) + sb1s[col];
                    accum += gelu_erf(v) * sw2s[col];
                }
            }
            asm volatile("tcgen05.fence::before_thread_sync;" ::: "memory");
            mbar_arrive(sb + OFF_EPI + p * 8);
        }
        const int row = warp * 32 + lane;
        out[(size_t)b * (NCLS * CDF) + (size_t)c * CDF + row] = accum + b2[c];
    }

    __syncthreads();
    if (warp == 8) {
        asm volatile("tcgen05.relinquish_alloc_permit.cta_group::1.sync.aligned;" ::: "memory");
        asm volatile("tcgen05.dealloc.cta_group::1.sync.aligned.b32 %0, %1;" :: "r"(tmem), "r"(512u));
    }
    // no CTA may exit while a peer's multicast into this CTA's smem is in flight
    asm volatile("barrier.cluster.arrive.aligned;" ::: "memory");
    asm volatile("barrier.cluster.wait.aligned;" ::: "memory");
#else
    (void)tmapB; (void)x; (void)b1; (void)W2; (void)b2; (void)out;
#endif
}

// ======================================================================
// Host
// ======================================================================
static void encode_tmap_b(CUtensorMap* tm, void* base) {
    typedef CUresult (*EncodeFn)(CUtensorMap*, CUtensorMapDataType, cuuint32_t, void*,
                                 const cuuint64_t*, const cuuint64_t*, const cuuint32_t*,
                                 const cuuint32_t*, CUtensorMapInterleave, CUtensorMapSwizzle,
                                 CUtensorMapL2promotion, CUtensorMapFloatOOBfill);
    EncodeFn fn = nullptr;
    cudaDriverEntryPointQueryResult qr;
#if CUDART_VERSION >= 12050
    cudaGetDriverEntryPointByVersion("cuTensorMapEncodeTiled", (void**)&fn, 12000,
                                     cudaEnableDefault, &qr);
#else
    cudaGetDriverEntryPoint("cuTensorMapEncodeTiled", (void**)&fn, cudaEnableDefault, &qr);
#endif
    if (!fn) return;
    cuuint64_t dims[3]    = {EDIM, EDIM, NCLS};                      // [k, n, c]
    cuuint64_t strides[2] = {EDIM * 4ull, (cuuint64_t)EDIM * EDIM * 4ull};
    cuuint32_t box[3]     = {32, 64, 1};                             // 32k x 64n slice (128B rows)
    cuuint32_t estr[3]    = {1, 1, 1};
    fn(tm, CU_TENSOR_MAP_DATA_TYPE_FLOAT32, 3, base, dims, strides, box, estr,
       CU_TENSOR_MAP_INTERLEAVE_NONE, CU_TENSOR_MAP_SWIZZLE_128B,
       CU_TENSOR_MAP_L2_PROMOTION_L2_128B, CU_TENSOR_MAP_FLOAT_OOB_FILL_NONE);
}

extern "C" void kernel_launch(void* const* d_in, const int* in_sizes, int n_in,
                              void* d_out, int out_size) {
    const float* x  = (const float*)d_in[0];
    const float* W1 = (const float*)d_in[1];
    const float* b1 = (const float*)d_in[2];
    const float* W2 = (const float*)d_in[3];
    const float* b2 = (const float*)d_in[4];
    float* out = (float*)d_out;

    void* w1t_ptr = nullptr;
    cudaGetSymbolAddress(&w1t_ptr, g_W1t);
    CUtensorMap tm;
    encode_tmap_b(&tm, w1t_ptr);

    cudaFuncSetAttribute(mlp_head_tc, cudaFuncAttributeMaxDynamicSharedMemorySize, SMEM_TOTAL);

    dim3 grid(BATCH, NCLS);

    w1_conv<<<dim3(EDIM / 32, EDIM / 32, NCLS), dim3(32, 8)>>>(W1);

    cudaLaunchConfig_t cfg = {};
    cfg.gridDim  = grid;
    cfg.blockDim = dim3(THREADS_TC, 1, 1);
    cfg.dynamicSmemBytes = SMEM_TOTAL;
    cfg.stream = 0;
    cudaLaunchAttribute attrs[1];
    attrs[0].id = cudaLaunchAttributeClusterDimension;
    attrs[0].val.clusterDim = {CLUSTER, 1, 1};   // 4 batch-CTAs share one class's W1
    cfg.attrs = attrs;
    cfg.numAttrs = 1;
    cudaLaunchKernelEx(&cfg, mlp_head_tc, tm, x, b1, W2, b2, out);
}